// round 7
// baseline (speedup 1.0000x reference)
#include <cuda_runtime.h>
#include <cuda_fp16.h>
#include <math.h>
#include <stdint.h>

#define NN   262144
#define HH   256
#define NV   65536
#define NG   512
#define NP   8
#define NHID 64

#define NTILES    4096      // NN / 64
#define GRID_MAIN 148

// ---------------- device globals ----------------
__device__ float  g_sums[NG * HH];
__device__ float  g_maxs[NG * HH];
__device__ float  g_gate[NV];
__device__ int    g_start[NG + 1];
__device__ __half g_Wt[HH * HH];    // W_pre transposed: Wt[n][k], fp16

// ---------------- helpers ----------------
__device__ __forceinline__ uint32_t smem_u32(const void* p) {
    uint32_t a;
    asm("{ .reg .u64 t; cvta.to.shared.u64 t, %1; cvt.u32.u64 %0, t; }" : "=r"(a) : "l"(p));
    return a;
}
__device__ __forceinline__ void cp16(uint32_t dst, const void* src) {
    asm volatile("cp.async.cg.shared.global [%0], [%1], 16;" :: "r"(dst), "l"(src));
}
__device__ __forceinline__ void atomicMaxF(float* addr, float v) {
    if (v >= 0.0f) atomicMax((int*)addr, __float_as_int(v));
    else           atomicMin((unsigned int*)addr, __float_as_uint(v));
}
#define LDMX4(r0,r1,r2,r3,addr) \
    asm volatile("ldmatrix.sync.aligned.m8n8.x4.shared.b16 {%0,%1,%2,%3}, [%4];" \
                 : "=r"(r0), "=r"(r1), "=r"(r2), "=r"(r3) : "r"(addr))
// f16-accumulator MMA: D(f16) = A*B + C(f16), 2 regs per fragment
#define MMA16816H(c0,c1,a0,a1,a2,a3,b0,b1) \
    asm volatile("mma.sync.aligned.m16n8k16.row.col.f16.f16.f16.f16 " \
                 "{%0,%1}, {%2,%3,%4,%5}, {%6,%7}, {%0,%1};" \
                 : "+r"(c0), "+r"(c1) \
                 : "r"(a0), "r"(a1), "r"(a2), "r"(a3), "r"(b0), "r"(b1))

// ---------------- prep: init + gate MLP + segment boundaries + W transpose ----------------
__global__ __launch_bounds__(256) void prep_kernel(
    const float* __restrict__ props,
    const float* __restrict__ W1, const float* __restrict__ b1,
    const float* __restrict__ W2, const float* __restrict__ b2,
    const float* __restrict__ Wpre,
    const int*   __restrict__ batch)
{
    __shared__ float sW1[NP * NHID];
    __shared__ float sb1[NHID];
    __shared__ float sW2[NHID];
    int tid = threadIdx.x;
    for (int i = tid; i < NP * NHID; i += 256) sW1[i] = W1[i];
    if (tid < NHID) { sb1[tid] = b1[tid]; sW2[tid] = W2[tid]; }
    __syncthreads();

    int idx = blockIdx.x * 256 + tid;     // 0..65535

    g_sums[idx] = 0.0f;          g_sums[idx + 65536] = 0.0f;
    g_maxs[idx] = -INFINITY;     g_maxs[idx + 65536] = -INFINITY;

    // Wt[n][k] = Wpre[k][n]
    {
        int k = idx >> 8, n = idx & 255;
        g_Wt[n * 256 + k] = __float2half(Wpre[idx]);
    }

    // segment boundary scan: 4 nodes per thread (batch is sorted)
    {
        int i0 = idx * 4;
        int4 b4 = *(const int4*)&batch[i0];
        int v[4] = {b4.x, b4.y, b4.z, b4.w};
        int p = (i0 == 0) ? -1 : batch[i0 - 1];
        #pragma unroll
        for (int e = 0; e < 4; e++) {
            for (int g = p + 1; g <= v[e]; g++) g_start[g] = i0 + e;
            p = v[e];
        }
        if (i0 + 4 == NN)
            for (int g = v[3] + 1; g <= NG; g++) g_start[g] = NN;
    }

    // gate MLP: 4 parallel hidden-unit chains + 2 accumulators
    {
        float4 p0 = ((const float4*)props)[idx * 2 + 0];
        float4 p1 = ((const float4*)props)[idx * 2 + 1];
        float pr[NP] = {p0.x, p0.y, p0.z, p0.w, p1.x, p1.y, p1.z, p1.w};
        float accA = b2[0], accB = 0.0f;
        #pragma unroll
        for (int j = 0; j < NHID; j += 4) {
            float s0 = sb1[j], s1 = sb1[j + 1], s2 = sb1[j + 2], s3 = sb1[j + 3];
            #pragma unroll
            for (int p2i = 0; p2i < NP; p2i++) {
                float pv = pr[p2i];
                const float* w = &sW1[p2i * NHID + j];
                s0 = fmaf(pv, w[0], s0);
                s1 = fmaf(pv, w[1], s1);
                s2 = fmaf(pv, w[2], s2);
                s3 = fmaf(pv, w[3], s3);
            }
            accA = fmaf(fmaxf(s0, 0.0f), sW2[j],     accA);
            accB = fmaf(fmaxf(s1, 0.0f), sW2[j + 1], accB);
            accA = fmaf(fmaxf(s2, 0.0f), sW2[j + 2], accA);
            accB = fmaf(fmaxf(s3, 0.0f), sW2[j + 3], accB);
        }
        g_gate[idx] = 1.0f / (1.0f + expf(-(accA + accB)));
    }
}

// ---------------- main: persistent HMMA GEMM (f16-acc chunks), B resident ----------------
// smem layout (204800 B dynamic):
//   B:        [0, 135168)            256 rows x 264 halfs (stride 528 B)
//   A stages: [135168, 135168+2*33792)  2 x (64 rows x 264 halfs)
//   misc:     [202752, 204800)       brow[2][64] int | wrow[2][64] f | sbias[256] f
#define B_BYTES  135168
#define A_OFF    135168
#define A_STAGE  33792
#define MISC_OFF 202752
#define SMEM_SZ  204800

__global__ __launch_bounds__(512, 1) void main_kernel(
    const float* __restrict__ emb,
    const int*   __restrict__ batch,
    const int*   __restrict__ ntype,
    const float* __restrict__ bpre)
{
    extern __shared__ char sm[];
    const uint32_t sbase = smem_u32(sm);
    int*   brow  = (int*)  (sm + MISC_OFF);            // [2][64]
    float* wrow  = (float*)(sm + MISC_OFF + 512);      // [2][64]
    float* sbias = (float*)(sm + MISC_OFF + 1024);     // [256]

    const int tid  = threadIdx.x;
    const int wid  = tid >> 5;
    const int lane = tid & 31;
    const int wm   = wid >> 2;     // 0..3: rows [wm*16, +16)
    const int wn   = wid & 3;      // 0..3: cols [wn*64, +64)

    // ---- load B once (persistent, 135 KB) ----
    #pragma unroll
    for (int i = 0; i < 16; i++) {
        int u = tid + i * 512;         // 0..8191
        int n = u >> 5, kc = u & 31;
        cp16(sbase + (uint32_t)(n * 528 + kc * 16),
             (const char*)g_Wt + (size_t)n * 512 + kc * 16);
    }
    asm volatile("cp.async.commit_group;" ::: "memory");

    if (tid < 256) sbias[tid] = bpre[tid];

    const int arow = tid >> 3;     // 0..63
    const int aseg = tid & 7;      // float4 slot; col floats = j*32 + aseg*4

    // ---- prologue: tile t0 -> stage 0 ----
    const int t0 = blockIdx.x;
    float4 ra[8];
    {
        const float* ap = emb + (size_t)(t0 * 64 + arow) * HH + aseg * 4;
        #pragma unroll
        for (int j = 0; j < 8; j++) ra[j] = *(const float4*)(ap + j * 32);
    }
    if (tid < 64) {
        int m = t0 * 64 + tid;
        brow[tid] = batch[m];
        wrow[tid] = (ntype[m] == 0) ? g_gate[m >> 2] : 1.0f;
    }
    {
        uint32_t base = sbase + A_OFF + (uint32_t)((arow * 264 + aseg * 4) * 2);
        #pragma unroll
        for (int j = 0; j < 8; j++) {
            __half2 h0 = __float22half2_rn(make_float2(ra[j].x, ra[j].y));
            __half2 h1 = __float22half2_rn(make_float2(ra[j].z, ra[j].w));
            asm volatile("st.shared.v2.b32 [%0], {%1,%2};"
                         :: "r"(base + j * 64),
                            "r"(*(uint32_t*)&h0), "r"(*(uint32_t*)&h1) : "memory");
        }
    }
    asm volatile("cp.async.wait_group 0;" ::: "memory");
    __syncthreads();

    // ldmatrix lane addresses (stride 264 halfs = odd multiple of 8 -> conflict-free)
    const uint32_t a_lm = sbase + A_OFF +
        (uint32_t)(((wm * 16 + (lane & 15)) * 264 + (lane >> 4) * 8) * 2);
    const uint32_t b_lm = sbase +
        (uint32_t)(((wn * 64 + (lane >> 4) * 8 + (lane & 7)) * 264 + ((lane >> 3) & 1) * 8) * 2);

    for (int t = t0, it = 0; t < NTILES; t += GRID_MAIN, it++) {
        const int cur = it & 1;
        const int nt  = t + GRID_MAIN;
        const bool hn = (nt < NTILES);

        if (hn) {
            const float* ap = emb + (size_t)(nt * 64 + arow) * HH + aseg * 4;
            #pragma unroll
            for (int j = 0; j < 8; j++) ra[j] = *(const float4*)(ap + j * 32);
            if (tid < 64) {
                int m = nt * 64 + tid;
                brow[(cur ^ 1) * 64 + tid] = batch[m];
                wrow[(cur ^ 1) * 64 + tid] = (ntype[m] == 0) ? g_gate[m >> 2] : 1.0f;
            }
        }

        float acc[8][4];
        #pragma unroll
        for (int ni = 0; ni < 8; ni++)
            #pragma unroll
            for (int r = 0; r < 4; r++) acc[ni][r] = 0.0f;

        const uint32_t ab = a_lm + (uint32_t)(cur * A_STAGE);
        // 8 chunk-pairs: accumulate K=32 in f16, promote to f32
        #pragma unroll
        for (int kp = 0; kp < 8; kp++) {
            uint32_t hacc[8][2];
            #pragma unroll
            for (int ni = 0; ni < 8; ni++) { hacc[ni][0] = 0u; hacc[ni][1] = 0u; }
            #pragma unroll
            for (int ks2 = 0; ks2 < 2; ks2++) {
                const int ks = kp * 2 + ks2;
                uint32_t af[4];
                LDMX4(af[0], af[1], af[2], af[3], ab + ks * 32);
                uint32_t bf[4][4];
                #pragma unroll
                for (int nip = 0; nip < 4; nip++)
                    LDMX4(bf[nip][0], bf[nip][1], bf[nip][2], bf[nip][3],
                          b_lm + nip * 8448 + ks * 32);
                #pragma unroll
                for (int ni = 0; ni < 8; ni++)
                    MMA16816H(hacc[ni][0], hacc[ni][1],
                              af[0], af[1], af[2], af[3],
                              bf[ni >> 1][(ni & 1) * 2], bf[ni >> 1][(ni & 1) * 2 + 1]);
            }
            #pragma unroll
            for (int ni = 0; ni < 8; ni++) {
                float2 lo = __half22float2(*reinterpret_cast<__half2*>(&hacc[ni][0]));
                float2 hi = __half22float2(*reinterpret_cast<__half2*>(&hacc[ni][1]));
                acc[ni][0] += lo.x; acc[ni][1] += lo.y;
                acc[ni][2] += hi.x; acc[ni][3] += hi.y;
            }
        }

        if (hn) {
            uint32_t base = sbase + A_OFF + (uint32_t)((cur ^ 1) * A_STAGE)
                          + (uint32_t)((arow * 264 + aseg * 4) * 2);
            #pragma unroll
            for (int j = 0; j < 8; j++) {
                __half2 h0 = __float22half2_rn(make_float2(ra[j].x, ra[j].y));
                __half2 h1 = __float22half2_rn(make_float2(ra[j].z, ra[j].w));
                asm volatile("st.shared.v2.b32 [%0], {%1,%2};"
                             :: "r"(base + j * 64),
                                "r"(*(uint32_t*)&h0), "r"(*(uint32_t*)&h1) : "memory");
            }
        }

        // ---- epilogue: bias + gate, shuffle segment-reduce, atomics ----
        {
            const int l1 = wm * 16 + (lane >> 2);
            const int l2 = l1 + 8;
            const int*   br = brow + cur * 64;
            const float* wr = wrow + cur * 64;
            const float w1 = wr[l1], w2 = wr[l2];
            #pragma unroll
            for (int ni = 0; ni < 8; ni++) {
                int c = wn * 64 + ni * 8 + (lane & 3) * 2;
                float b0 = sbias[c], b1 = sbias[c + 1];
                acc[ni][0] = (acc[ni][0] + b0) * w1;
                acc[ni][1] = (acc[ni][1] + b1) * w1;
                acc[ni][2] = (acc[ni][2] + b0) * w2;
                acc[ni][3] = (acc[ni][3] + b1) * w2;
            }
            const int glo = br[wm * 16], ghi = br[wm * 16 + 15];
            const int bg1 = br[l1], bg2 = br[l2];
            for (int g = glo; g <= ghi; g++) {
                const bool p1 = (bg1 == g), p2 = (bg2 == g);
                #pragma unroll
                for (int ni = 0; ni < 8; ni++) {
                    float s0 = (p1 ? acc[ni][0] : 0.0f) + (p2 ? acc[ni][2] : 0.0f);
                    float s1 = (p1 ? acc[ni][1] : 0.0f) + (p2 ? acc[ni][3] : 0.0f);
                    float m0v = fmaxf(p1 ? acc[ni][0] : -INFINITY, p2 ? acc[ni][2] : -INFINITY);
                    float m1v = fmaxf(p1 ? acc[ni][1] : -INFINITY, p2 ? acc[ni][3] : -INFINITY);
                    #pragma unroll
                    for (int off = 4; off < 32; off <<= 1) {
                        s0  += __shfl_xor_sync(0xffffffffu, s0,  off);
                        s1  += __shfl_xor_sync(0xffffffffu, s1,  off);
                        m0v = fmaxf(m0v, __shfl_xor_sync(0xffffffffu, m0v, off));
                        m1v = fmaxf(m1v, __shfl_xor_sync(0xffffffffu, m1v, off));
                    }
                    if (lane < 4) {
                        int c = wn * 64 + ni * 8 + lane * 2;
                        atomicAdd(&g_sums[g * HH + c],     s0);
                        atomicAdd(&g_sums[g * HH + c + 1], s1);
                        if (m0v > -INFINITY) atomicMaxF(&g_maxs[g * HH + c],     m0v);
                        if (m1v > -INFINITY) atomicMaxF(&g_maxs[g * HH + c + 1], m1v);
                    }
                }
            }
        }
        __syncthreads();
    }
}

// ---------------- final linear ----------------
__global__ __launch_bounds__(256) void final_kernel(
    const float* __restrict__ Wpost,
    const float* __restrict__ bpost,
    float* __restrict__ out)
{
    __shared__ float comb[8][2 * HH];
    __shared__ float invc[8];
    int tid = threadIdx.x;
    int g0 = blockIdx.x * 8;

    if (tid < 8) {
        int g = g0 + tid;
        int c = g_start[g + 1] - g_start[g];
        invc[tid] = 1.0f / fmaxf((float)c, 1.0f);
    }
    __syncthreads();

    for (int idx = tid; idx < 8 * 2 * HH; idx += 256) {
        int g = idx >> 9;
        int k = idx & 511;
        float v;
        if (k < HH) {
            v = g_sums[(size_t)(g0 + g) * HH + k] * invc[g];
        } else {
            float m = g_maxs[(size_t)(g0 + g) * HH + (k - HH)];
            v = isfinite(m) ? m : 0.0f;
        }
        comb[g][k] = v;
    }
    __syncthreads();

    float acc[8];
    #pragma unroll
    for (int g = 0; g < 8; g++) acc[g] = 0.0f;

    for (int k = 0; k < 2 * HH; k++) {
        float wv = Wpost[(size_t)k * HH + tid];
        #pragma unroll
        for (int g = 0; g < 8; g++) acc[g] = fmaf(comb[g][k], wv, acc[g]);
    }
    float bb = bpost[tid];
    #pragma unroll
    for (int g = 0; g < 8; g++)
        out[(size_t)(g0 + g) * HH + tid] = acc[g] + bb;
}

// ---------------- launch ----------------
extern "C" void kernel_launch(void* const* d_in, const int* in_sizes, int n_in,
                              void* d_out, int out_size)
{
    const float* emb   = (const float*)d_in[0];
    const int*   batch = (const int*)  d_in[1];
    const float* props = (const float*)d_in[2];
    const int*   ntype = (const int*)  d_in[3];
    const float* Wpre  = (const float*)d_in[4];
    const float* bpre  = (const float*)d_in[5];
    const float* W1    = (const float*)d_in[6];
    const float* b1    = (const float*)d_in[7];
    const float* W2    = (const float*)d_in[8];
    const float* b2    = (const float*)d_in[9];
    const float* Wpost = (const float*)d_in[10];
    const float* bpost = (const float*)d_in[11];
    float* out = (float*)d_out;

    cudaFuncSetAttribute(main_kernel, cudaFuncAttributeMaxDynamicSharedMemorySize, SMEM_SZ);

    prep_kernel<<<256, 256>>>(props, W1, b1, W2, b2, Wpre, batch);
    main_kernel<<<GRID_MAIN, 512, SMEM_SZ>>>(emb, batch, ntype, bpre);
    final_kernel<<<NG / 8, 256>>>(Wpost, bpost, out);
}

// round 8
// speedup vs baseline: 1.0575x; 1.0575x over previous
#include <cuda_runtime.h>
#include <cuda_fp16.h>
#include <math.h>
#include <stdint.h>

#define NN   262144
#define HH   256
#define NV   65536
#define NG   512
#define NP   8
#define NHID 64

#define NTILES    4096      // NN / 64
#define GRID_MAIN 148

// ---------------- device globals ----------------
__device__ float  g_sums[NG * HH];
__device__ float  g_maxs[NG * HH];
__device__ float  g_gate[NV];
__device__ int    g_start[NG + 1];
__device__ __half g_Wt[HH * HH];    // W_pre transposed: Wt[n][k], fp16

// ---------------- helpers ----------------
__device__ __forceinline__ uint32_t smem_u32(const void* p) {
    uint32_t a;
    asm("{ .reg .u64 t; cvta.to.shared.u64 t, %1; cvt.u32.u64 %0, t; }" : "=r"(a) : "l"(p));
    return a;
}
__device__ __forceinline__ void cp16(uint32_t dst, const void* src) {
    asm volatile("cp.async.cg.shared.global [%0], [%1], 16;" :: "r"(dst), "l"(src));
}
__device__ __forceinline__ void atomicMaxF(float* addr, float v) {
    if (v >= 0.0f) atomicMax((int*)addr, __float_as_int(v));
    else           atomicMin((unsigned int*)addr, __float_as_uint(v));
}
#define LDMX4(r0,r1,r2,r3,addr) \
    asm volatile("ldmatrix.sync.aligned.m8n8.x4.shared.b16 {%0,%1,%2,%3}, [%4];" \
                 : "=r"(r0), "=r"(r1), "=r"(r2), "=r"(r3) : "r"(addr))
#define MMA16816(c0,c1,c2,c3,a0,a1,a2,a3,b0,b1) \
    asm volatile("mma.sync.aligned.m16n8k16.row.col.f32.f16.f16.f32 " \
                 "{%0,%1,%2,%3}, {%4,%5,%6,%7}, {%8,%9}, {%0,%1,%2,%3};" \
                 : "+f"(c0), "+f"(c1), "+f"(c2), "+f"(c3) \
                 : "r"(a0), "r"(a1), "r"(a2), "r"(a3), "r"(b0), "r"(b1))

// ---------------- prep: 1024 x 64 for SM balance ----------------
__global__ __launch_bounds__(64) void prep_kernel(
    const float* __restrict__ props,
    const float* __restrict__ W1, const float* __restrict__ b1,
    const float* __restrict__ W2, const float* __restrict__ b2,
    const float* __restrict__ Wpre,
    const int*   __restrict__ batch)
{
    int tid = threadIdx.x;
    int idx = blockIdx.x * 64 + tid;      // 0..65535

    g_sums[idx] = 0.0f;          g_sums[idx + 65536] = 0.0f;
    g_maxs[idx] = -INFINITY;     g_maxs[idx + 65536] = -INFINITY;

    // Wt[n][k] = Wpre[k][n]
    {
        int k = idx >> 8, n = idx & 255;
        g_Wt[n * 256 + k] = __float2half(Wpre[idx]);
    }

    // segment boundary scan: 4 nodes per thread (batch is sorted)
    {
        int i0 = idx * 4;
        int4 b4 = *(const int4*)&batch[i0];
        int v[4] = {b4.x, b4.y, b4.z, b4.w};
        int p = (i0 == 0) ? -1 : batch[i0 - 1];
        #pragma unroll
        for (int e = 0; e < 4; e++) {
            for (int g = p + 1; g <= v[e]; g++) g_start[g] = i0 + e;
            p = v[e];
        }
        if (i0 + 4 == NN)
            for (int g = v[3] + 1; g <= NG; g++) g_start[g] = NN;
    }

    // gate MLP: 4 parallel hidden-unit chains, weights via L1/L2 (read-only cache)
    {
        float4 p0 = __ldg((const float4*)props + idx * 2);
        float4 p1 = __ldg((const float4*)props + idx * 2 + 1);
        float pr[NP] = {p0.x, p0.y, p0.z, p0.w, p1.x, p1.y, p1.z, p1.w};
        float accA = __ldg(b2), accB = 0.0f;
        #pragma unroll
        for (int j = 0; j < NHID; j += 4) {
            float s0 = __ldg(b1 + j),     s1 = __ldg(b1 + j + 1);
            float s2 = __ldg(b1 + j + 2), s3 = __ldg(b1 + j + 3);
            #pragma unroll
            for (int p2i = 0; p2i < NP; p2i++) {
                float pv = pr[p2i];
                const float* w = W1 + p2i * NHID + j;
                s0 = fmaf(pv, __ldg(w),     s0);
                s1 = fmaf(pv, __ldg(w + 1), s1);
                s2 = fmaf(pv, __ldg(w + 2), s2);
                s3 = fmaf(pv, __ldg(w + 3), s3);
            }
            accA = fmaf(fmaxf(s0, 0.0f), __ldg(W2 + j),     accA);
            accB = fmaf(fmaxf(s1, 0.0f), __ldg(W2 + j + 1), accB);
            accA = fmaf(fmaxf(s2, 0.0f), __ldg(W2 + j + 2), accA);
            accB = fmaf(fmaxf(s3, 0.0f), __ldg(W2 + j + 3), accB);
        }
        g_gate[idx] = 1.0f / (1.0f + expf(-(accA + accB)));
    }
}

// ---------------- main: persistent HMMA GEMM, B resident in smem ----------------
// smem layout (204800 B dynamic):
//   B:        [0, 135168)            256 rows x 264 halfs (stride 528 B)
//   A stages: [135168, 135168+2*33792)  2 x (64 rows x 264 halfs)
//   misc:     [202752, 204800)       brow[2][64] int | wrow[2][64] f | sbias[256] f
#define B_BYTES  135168
#define A_OFF    135168
#define A_STAGE  33792
#define MISC_OFF 202752
#define SMEM_SZ  204800

__global__ __launch_bounds__(512, 1) void main_kernel(
    const float* __restrict__ emb,
    const int*   __restrict__ batch,
    const int*   __restrict__ ntype,
    const float* __restrict__ bpre)
{
    extern __shared__ char sm[];
    const uint32_t sbase = smem_u32(sm);
    int*   brow  = (int*)  (sm + MISC_OFF);            // [2][64]
    float* wrow  = (float*)(sm + MISC_OFF + 512);      // [2][64]
    float* sbias = (float*)(sm + MISC_OFF + 1024);     // [256]

    const int tid  = threadIdx.x;
    const int wid  = tid >> 5;
    const int lane = tid & 31;
    const int wm   = wid >> 2;     // 0..3: rows [wm*16, +16)
    const int wn   = wid & 3;      // 0..3: cols [wn*64, +64)

    // ---- load B once (persistent, 135 KB) ----
    #pragma unroll
    for (int i = 0; i < 16; i++) {
        int u = tid + i * 512;         // 0..8191
        int n = u >> 5, kc = u & 31;
        cp16(sbase + (uint32_t)(n * 528 + kc * 16),
             (const char*)g_Wt + (size_t)n * 512 + kc * 16);
    }
    asm volatile("cp.async.commit_group;" ::: "memory");

    if (tid < 256) sbias[tid] = bpre[tid];

    const int arow = tid >> 3;     // 0..63
    const int aseg = tid & 7;      // float4 slot; col floats = j*32 + aseg*4

    // ---- prologue: tile t0 -> stage 0 ----
    const int t0 = blockIdx.x;
    float4 ra[8];
    {
        const float* ap = emb + (size_t)(t0 * 64 + arow) * HH + aseg * 4;
        #pragma unroll
        for (int j = 0; j < 8; j++) ra[j] = *(const float4*)(ap + j * 32);
    }
    if (tid < 64) {
        int m = t0 * 64 + tid;
        brow[tid] = batch[m];
        wrow[tid] = (ntype[m] == 0) ? g_gate[m >> 2] : 1.0f;
    }
    {
        uint32_t base = sbase + A_OFF + (uint32_t)((arow * 264 + aseg * 4) * 2);
        #pragma unroll
        for (int j = 0; j < 8; j++) {
            __half2 h0 = __float22half2_rn(make_float2(ra[j].x, ra[j].y));
            __half2 h1 = __float22half2_rn(make_float2(ra[j].z, ra[j].w));
            asm volatile("st.shared.v2.b32 [%0], {%1,%2};"
                         :: "r"(base + j * 64),
                            "r"(*(uint32_t*)&h0), "r"(*(uint32_t*)&h1) : "memory");
        }
    }
    asm volatile("cp.async.wait_group 0;" ::: "memory");
    __syncthreads();

    // ldmatrix lane addresses (stride 264 halfs = odd multiple of 8 -> conflict-free)
    const uint32_t a_lm = sbase + A_OFF +
        (uint32_t)(((wm * 16 + (lane & 15)) * 264 + (lane >> 4) * 8) * 2);
    const uint32_t b_lm = sbase +
        (uint32_t)(((wn * 64 + (lane >> 4) * 8 + (lane & 7)) * 264 + ((lane >> 3) & 1) * 8) * 2);

    for (int t = t0, it = 0; t < NTILES; t += GRID_MAIN, it++) {
        const int cur = it & 1;
        const int nt  = t + GRID_MAIN;
        const bool hn = (nt < NTILES);

        if (hn) {
            const float* ap = emb + (size_t)(nt * 64 + arow) * HH + aseg * 4;
            #pragma unroll
            for (int j = 0; j < 8; j++) ra[j] = *(const float4*)(ap + j * 32);
            if (tid < 64) {
                int m = nt * 64 + tid;
                brow[(cur ^ 1) * 64 + tid] = batch[m];
                wrow[(cur ^ 1) * 64 + tid] = (ntype[m] == 0) ? g_gate[m >> 2] : 1.0f;
            }
        }

        float acc[8][4];
        #pragma unroll
        for (int ni = 0; ni < 8; ni++)
            #pragma unroll
            for (int r = 0; r < 4; r++) acc[ni][r] = 0.0f;

        const uint32_t ab = a_lm + (uint32_t)(cur * A_STAGE);
        #pragma unroll
        for (int ks = 0; ks < 16; ks++) {
            uint32_t af[4];
            LDMX4(af[0], af[1], af[2], af[3], ab + ks * 32);
            uint32_t bf[4][4];
            #pragma unroll
            for (int nip = 0; nip < 4; nip++)
                LDMX4(bf[nip][0], bf[nip][1], bf[nip][2], bf[nip][3],
                      b_lm + nip * 8448 + ks * 32);
            #pragma unroll
            for (int ni = 0; ni < 8; ni++)
                MMA16816(acc[ni][0], acc[ni][1], acc[ni][2], acc[ni][3],
                         af[0], af[1], af[2], af[3],
                         bf[ni >> 1][(ni & 1) * 2], bf[ni >> 1][(ni & 1) * 2 + 1]);
        }

        if (hn) {
            uint32_t base = sbase + A_OFF + (uint32_t)((cur ^ 1) * A_STAGE)
                          + (uint32_t)((arow * 264 + aseg * 4) * 2);
            #pragma unroll
            for (int j = 0; j < 8; j++) {
                __half2 h0 = __float22half2_rn(make_float2(ra[j].x, ra[j].y));
                __half2 h1 = __float22half2_rn(make_float2(ra[j].z, ra[j].w));
                asm volatile("st.shared.v2.b32 [%0], {%1,%2};"
                             :: "r"(base + j * 64),
                                "r"(*(uint32_t*)&h0), "r"(*(uint32_t*)&h1) : "memory");
            }
        }

        // ---- epilogue: bias + gate, shuffle segment-reduce, atomics ----
        {
            const int l1 = wm * 16 + (lane >> 2);
            const int l2 = l1 + 8;
            const int*   br = brow + cur * 64;
            const float* wr = wrow + cur * 64;
            const float w1 = wr[l1], w2 = wr[l2];
            #pragma unroll
            for (int ni = 0; ni < 8; ni++) {
                int c = wn * 64 + ni * 8 + (lane & 3) * 2;
                float b0 = sbias[c], b1 = sbias[c + 1];
                acc[ni][0] = (acc[ni][0] + b0) * w1;
                acc[ni][1] = (acc[ni][1] + b1) * w1;
                acc[ni][2] = (acc[ni][2] + b0) * w2;
                acc[ni][3] = (acc[ni][3] + b1) * w2;
            }
            const int glo = br[wm * 16], ghi = br[wm * 16 + 15];
            const int bg1 = br[l1], bg2 = br[l2];
            for (int g = glo; g <= ghi; g++) {
                const bool p1 = (bg1 == g), p2 = (bg2 == g);
                #pragma unroll
                for (int ni = 0; ni < 8; ni++) {
                    float s0 = (p1 ? acc[ni][0] : 0.0f) + (p2 ? acc[ni][2] : 0.0f);
                    float s1 = (p1 ? acc[ni][1] : 0.0f) + (p2 ? acc[ni][3] : 0.0f);
                    float m0v = fmaxf(p1 ? acc[ni][0] : -INFINITY, p2 ? acc[ni][2] : -INFINITY);
                    float m1v = fmaxf(p1 ? acc[ni][1] : -INFINITY, p2 ? acc[ni][3] : -INFINITY);
                    #pragma unroll
                    for (int off = 4; off < 32; off <<= 1) {
                        s0  += __shfl_xor_sync(0xffffffffu, s0,  off);
                        s1  += __shfl_xor_sync(0xffffffffu, s1,  off);
                        m0v = fmaxf(m0v, __shfl_xor_sync(0xffffffffu, m0v, off));
                        m1v = fmaxf(m1v, __shfl_xor_sync(0xffffffffu, m1v, off));
                    }
                    if (lane < 4) {
                        int c = wn * 64 + ni * 8 + lane * 2;
                        atomicAdd(&g_sums[g * HH + c],     s0);
                        atomicAdd(&g_sums[g * HH + c + 1], s1);
                        if (m0v > -INFINITY) atomicMaxF(&g_maxs[g * HH + c],     m0v);
                        if (m1v > -INFINITY) atomicMaxF(&g_maxs[g * HH + c + 1], m1v);
                    }
                }
            }
        }
        __syncthreads();
    }
}

// ---------------- final linear ----------------
__global__ __launch_bounds__(256) void final_kernel(
    const float* __restrict__ Wpost,
    const float* __restrict__ bpost,
    float* __restrict__ out)
{
    __shared__ float comb[8][2 * HH];
    __shared__ float invc[8];
    int tid = threadIdx.x;
    int g0 = blockIdx.x * 8;

    if (tid < 8) {
        int g = g0 + tid;
        int c = g_start[g + 1] - g_start[g];
        invc[tid] = 1.0f / fmaxf((float)c, 1.0f);
    }
    __syncthreads();

    for (int idx = tid; idx < 8 * 2 * HH; idx += 256) {
        int g = idx >> 9;
        int k = idx & 511;
        float v;
        if (k < HH) {
            v = g_sums[(size_t)(g0 + g) * HH + k] * invc[g];
        } else {
            float m = g_maxs[(size_t)(g0 + g) * HH + (k - HH)];
            v = isfinite(m) ? m : 0.0f;
        }
        comb[g][k] = v;
    }
    __syncthreads();

    float acc[8];
    #pragma unroll
    for (int g = 0; g < 8; g++) acc[g] = 0.0f;

    for (int k = 0; k < 2 * HH; k++) {
        float wv = Wpost[(size_t)k * HH + tid];
        #pragma unroll
        for (int g = 0; g < 8; g++) acc[g] = fmaf(comb[g][k], wv, acc[g]);
    }
    float bb = bpost[tid];
    #pragma unroll
    for (int g = 0; g < 8; g++)
        out[(size_t)(g0 + g) * HH + tid] = acc[g] + bb;
}

// ---------------- launch ----------------
extern "C" void kernel_launch(void* const* d_in, const int* in_sizes, int n_in,
                              void* d_out, int out_size)
{
    const float* emb   = (const float*)d_in[0];
    const int*   batch = (const int*)  d_in[1];
    const float* props = (const float*)d_in[2];
    const int*   ntype = (const int*)  d_in[3];
    const float* Wpre  = (const float*)d_in[4];
    const float* bpre  = (const float*)d_in[5];
    const float* W1    = (const float*)d_in[6];
    const float* b1    = (const float*)d_in[7];
    const float* W2    = (const float*)d_in[8];
    const float* b2    = (const float*)d_in[9];
    const float* Wpost = (const float*)d_in[10];
    const float* bpost = (const float*)d_in[11];
    float* out = (float*)d_out;

    cudaFuncSetAttribute(main_kernel, cudaFuncAttributeMaxDynamicSharedMemorySize, SMEM_SZ);

    prep_kernel<<<1024, 64>>>(props, W1, b1, W2, b2, Wpre, batch);
    main_kernel<<<GRID_MAIN, 512, SMEM_SZ>>>(emb, batch, ntype, bpre);
    final_kernel<<<NG / 8, 256>>>(Wpost, bpost, out);
}